// round 7
// baseline (speedup 1.0000x reference)
#include <cuda_runtime.h>
#include <math.h>
#include <stdint.h>

#define B_ 32
#define N_ 4096
#define M_ 128
#define TOT_ (B_ * M_)       // 4096 matched pairs total
#define LSA_T 512
#define KPT (N_ / LSA_T)     // 8 columns per thread (strided: j = tid + 512k)
#define NW_ (LSA_T / 32)     // 16 warps
#define MARGIN 1e-2f         // fp32 filter slack (>=400x worst-case fp32 err)

// Cost matrix scratch, stored TRANSPOSED: cost_t[b][m][n] = cost[b][n][m].
__device__ float g_cost[(size_t)B_ * M_ * N_];

// ---------------------------------------------------------------------------
// Kernel 1: cost matrix (full-chip parallel, one CTA per (b, m) row).
// ---------------------------------------------------------------------------
__global__ void cost_kernel(const float* __restrict__ ps,
                            const float* __restrict__ pp,
                            const int*   __restrict__ sc,
                            const float* __restrict__ pt) {
    int bm = blockIdx.x;
    int b  = bm >> 7;
    int m  = bm & (M_ - 1);
    int s  = sc[b * M_ + m];
    float qx = pt[(b * M_ + m) * 2 + 0];
    float qy = pt[(b * M_ + m) * 2 + 1];
    float* out = g_cost + (size_t)bm * N_;
    const float2* psb = ((const float2*)ps) + (size_t)b * N_;
    const float2* ppb = ((const float2*)pp) + (size_t)b * N_;
    for (int n = threadIdx.x; n < N_; n += blockDim.x) {
        float2 l = psb[n];
        float mx = fmaxf(l.x, l.y);
        float e0 = expf(l.x - mx);
        float e1 = expf(l.y - mx);
        float p  = ((s == 0) ? e0 : e1) / (e0 + e1);
        float2 q = ppb[n];
        float l1 = fabsf(q.x - qx) + fabsf(q.y - qy);
        out[n] = -p + l1;
    }
}

// Order-preserving bijection double <-> uint64 (total order, exact).
__device__ __forceinline__ unsigned long long dkey(double x) {
    unsigned long long u = (unsigned long long)__double_as_longlong(x);
    unsigned long long m = (unsigned long long)((long long)u >> 63);
    return u ^ (m | 0x8000000000000000ULL);
}
__device__ __forceinline__ double dunkey(unsigned long long k) {
    unsigned long long u = (k & 0x8000000000000000ULL)
                         ? (k ^ 0x8000000000000000ULL) : ~k;
    return __longlong_as_double((long long)u);
}

#define INFKEY 0xFFF0000000000000ULL   /* dkey(+inf) */
#define POPKEY 0xFFFFFFFFFFFFFFFFULL   /* > INFKEY: excluded from argmin */

// ---------------------------------------------------------------------------
// Kernel 2: Jonker-Volgenant, one CTA per batch. n=128 rows, m=4096 cols.
// All FP64 VALUES bit-match the reference; comparisons on exact u64 keys.
// FP32 pre-filter skips provably-non-improving columns (conservative margin).
// All per-column state in registers (constant-index unrolled access only).
// ---------------------------------------------------------------------------
__global__ __launch_bounds__(LSA_T) void lsa_kernel(float* __restrict__ out) {
    const int b   = blockIdx.x;
    const int tid = threadIdx.x;

    __shared__ double             u[M_];
    __shared__ unsigned long long red_key[2][NW_]; // parity double-buffer
    __shared__ int                red_idx[2][NW_];
    __shared__ unsigned long long hist_k[M_ + 1];  // pop-time min key
    __shared__ short              hist_j[M_ + 1];  // popped column
    __shared__ short              col4row[M_];     // row -> col (or -1)
    __shared__ signed char        row4col[N_];     // col -> row (or -1)
    __shared__ unsigned char      path_sm[N_];     // predecessor row per col

    const float* costb = g_cost + (size_t)b * M_ * N_;
    const float  FINF  = __int_as_float(0x7f800000);

    double v_loc[KPT];                             // exact v[tid + 512k]
    float  v32f[KPT];                              // fp32 shadow of v
    #pragma unroll
    for (int k = 0; k < KPT; ++k) { v_loc[k] = 0.0; v32f[k] = 0.0f; }

    for (int j = tid; j < N_; j += LSA_T) row4col[j] = -1;
    if (tid < M_) { u[tid] = 0.0; col4row[tid] = -1; }
    __syncthreads();

    for (int cur = 0; cur < M_; ++cur) {
        // ---- per-augmentation init: registers only, no smem zeroing ----
        unsigned long long sk[KPT];                // key(shortest[j]) exact
        float              s32m[KPT];              // fp32 bound + MARGIN
        #pragma unroll
        for (int k = 0; k < KPT; ++k) { sk[k] = INFKEY; s32m[k] = FINF; }
        unsigned long long bkey = POPKEY;          // thread-local argmin
        int                bidx = N_;

        int    i    = cur;
        double mv   = 0.0;
        double u_i  = u[cur];
        int    S    = 0;
        int    sink = -1;

        // ---- Dijkstra: ONE barrier per step ----
        while (true) {
            const float mv32 = (float)mv;
            const float u32  = (float)u_i;
            const float* crow = costb + (size_t)i * N_;

            float c[KPT];
            #pragma unroll
            for (int k = 0; k < KPT; ++k) c[k] = __ldg(crow + tid + k * LSA_T);

            #pragma unroll
            for (int k = 0; k < KPT; ++k) {
                const int j = tid + k * LSA_T;
                // fp32 filter: skip unless possibly improving (popped: s32m=-inf)
                float r32 = ((mv32 + c[k]) - u32) - v32f[k];
                if (r32 < s32m[k]) {
                    // exact numpy order: ((min_val + Cm[i,j]) - u[i]) - v[j]
                    double r = ((mv + (double)c[k]) - u_i) - v_loc[k];
                    unsigned long long rk = dkey(r);
                    if (rk < sk[k]) {
                        sk[k]   = rk;
                        s32m[k] = (float)r + MARGIN;
                        path_sm[j] = (unsigned char)i;
                        if (rk < bkey || (rk == bkey && j < bidx)) {
                            bkey = rk; bidx = j;
                        }
                    }
                }
            }

            // warp argmin (tie-break: smaller column index)
            unsigned long long wk = bkey;
            int                wi = bidx;
            #pragma unroll
            for (int off = 16; off > 0; off >>= 1) {
                unsigned long long ok = __shfl_down_sync(0xffffffffu, wk, off);
                int                oi = __shfl_down_sync(0xffffffffu, wi, off);
                if (ok < wk || (ok == wk && oi < wi)) { wk = ok; wi = oi; }
            }
            const int p = S & 1;
            if ((tid & 31) == 0) { red_key[p][tid >> 5] = wk; red_idx[p][tid >> 5] = wi; }
            __syncthreads();

            // every thread scans 16 warp minima -> identical decision
            unsigned long long kmin = red_key[p][0];
            int                jmin = red_idx[p][0];
            #pragma unroll
            for (int w = 1; w < NW_; ++w) {
                unsigned long long kk = red_key[p][w];
                int                jj = red_idx[p][w];
                if (kk < kmin || (kk == kmin && jj < jmin)) { kmin = kk; jmin = jj; }
            }
            if (tid == 0) { hist_k[S] = kmin; hist_j[S] = (short)jmin; }
            S++;

            // owner retires the popped column (constant-index unrolled)
            if ((jmin & (LSA_T - 1)) == tid) {
                #pragma unroll
                for (int k = 0; k < KPT; ++k)
                    if (jmin == tid + k * LSA_T) { sk[k] = POPKEY; s32m[k] = -FINF; }
            }
            // recompute local argmin only if our candidate was just popped
            if (bidx == jmin) {
                bkey = POPKEY; bidx = N_;
                #pragma unroll
                for (int k = 0; k < KPT; ++k) {
                    if (sk[k] < bkey) { bkey = sk[k]; bidx = tid + k * LSA_T; }
                }
            }

            mv = dunkey(kmin);
            int rc = row4col[jmin];
            if (rc < 0) { sink = jmin; break; }
            i   = rc;
            u_i = u[i];
        }
        __syncthreads();    // hist + path + relax complete everywhere

        // ---- dual update from pop history ----
        const double mvf = mv;
        if (tid == cur) u[cur] += mvf;
        if (tid < S - 1) {                         // non-sink pops
            int js = hist_j[tid];
            int r  = row4col[js];                  // pre-augment matching
            u[r] += mvf - dunkey(hist_k[tid]);
        }
        for (int s = 0; s < S; ++s) {              // v over popped cols
            int js = hist_j[s];
            if ((js & (LSA_T - 1)) == tid) {
                double d  = mvf - dunkey(hist_k[s]);
                int    kk = js >> 9;
                #pragma unroll
                for (int k = 0; k < KPT; ++k)      // constant-index only
                    if (kk == k) v_loc[k] -= d;
            }
        }
        #pragma unroll
        for (int k = 0; k < KPT; ++k) v32f[k] = (float)v_loc[k];
        __syncthreads();    // dual reads of row4col done before augment writes

        // ---- augment along alternating path ----
        if (tid == 0) {
            int j = sink;
            while (true) {
                int i2 = path_sm[j];
                row4col[j] = (signed char)i2;
                int t = col4row[i2]; col4row[i2] = (short)j; j = t;
                if (i2 == cur) break;
            }
        }
        __syncthreads();
    }

    // ---- emit (batch, src, tgt) as FLOAT32, sorted by src ----
    if (tid < M_) {
        int c = col4row[tid];
        int rank = 0;
        #pragma unroll 8
        for (int k = 0; k < M_; ++k) rank += (col4row[k] < c);
        int base = b * M_ + rank;
        out[0 * TOT_ + base] = (float)b;
        out[1 * TOT_ + base] = (float)c;
        out[2 * TOT_ + base] = (float)tid;
    }
}

// ---------------------------------------------------------------------------
extern "C" void kernel_launch(void* const* d_in, const int* in_sizes, int n_in,
                              void* d_out, int out_size) {
    const float* ps = (const float*)d_in[0];
    const float* pp = (const float*)d_in[1];
    const int*   sc = (const int*)  d_in[2];
    const float* pt = (const float*)d_in[3];

    cost_kernel<<<B_ * M_, 256>>>(ps, pp, sc, pt);
    lsa_kernel<<<B_, LSA_T>>>((float*)d_out);
}

// round 10
// speedup vs baseline: 1.5262x; 1.5262x over previous
#include <cuda_runtime.h>
#include <math.h>
#include <stdint.h>

#define B_ 32
#define N_ 4096
#define M_ 128
#define TOT_ (B_ * M_)       // 4096 matched pairs total
#define LSA_T 512
#define KPT (N_ / LSA_T)     // 8 columns per thread (strided: j = tid + 512k)
#define NW_ (LSA_T / 32)     // 16 warps

// Cost matrix scratch, stored TRANSPOSED: cost_t[b][m][n] = cost[b][n][m].
__device__ float g_cost[(size_t)B_ * M_ * N_];
// Row minima of the transposed matrix: umin[b][m] = min_n cost_t[b][m][n].
__device__ float g_umin[B_ * M_];

// ---------------------------------------------------------------------------
// Kernel 1: cost matrix + row-min (one CTA per (b, m) row).
// ---------------------------------------------------------------------------
__global__ void cost_kernel(const float* __restrict__ ps,
                            const float* __restrict__ pp,
                            const int*   __restrict__ sc,
                            const float* __restrict__ pt) {
    int bm = blockIdx.x;
    int b  = bm >> 7;
    int m  = bm & (M_ - 1);
    int s  = sc[b * M_ + m];
    float qx = pt[(b * M_ + m) * 2 + 0];
    float qy = pt[(b * M_ + m) * 2 + 1];
    float* out = g_cost + (size_t)bm * N_;
    const float2* psb = ((const float2*)ps) + (size_t)b * N_;
    const float2* ppb = ((const float2*)pp) + (size_t)b * N_;

    float lmin = __int_as_float(0x7f800000);
    for (int n = threadIdx.x; n < N_; n += blockDim.x) {
        float2 l = psb[n];
        float mx = fmaxf(l.x, l.y);
        float e0 = expf(l.x - mx);
        float e1 = expf(l.y - mx);
        float p  = ((s == 0) ? e0 : e1) / (e0 + e1);
        float2 q = ppb[n];
        float l1 = fabsf(q.x - qx) + fabsf(q.y - qy);
        float c  = -p + l1;
        out[n] = c;
        lmin = fminf(lmin, c);
    }
    // block-reduce min (256 threads = 8 warps)
    __shared__ float red[8];
    #pragma unroll
    for (int off = 16; off > 0; off >>= 1)
        lmin = fminf(lmin, __shfl_xor_sync(0xffffffffu, lmin, off));
    if ((threadIdx.x & 31) == 0) red[threadIdx.x >> 5] = lmin;
    __syncthreads();
    if (threadIdx.x == 0) {
        float r = red[0];
        #pragma unroll
        for (int w = 1; w < 8; ++w) r = fminf(r, red[w]);
        g_umin[bm] = r;
    }
}

// Order-preserving bijection double <-> uint64 (total order, exact).
__device__ __forceinline__ unsigned long long dkey(double x) {
    unsigned long long u = (unsigned long long)__double_as_longlong(x);
    unsigned long long m = (unsigned long long)((long long)u >> 63);
    return u ^ (m | 0x8000000000000000ULL);
}
__device__ __forceinline__ double dunkey(unsigned long long k) {
    unsigned long long u = (k & 0x8000000000000000ULL)
                         ? (k ^ 0x8000000000000000ULL) : ~k;
    return __longlong_as_double((long long)u);
}

#define INFKEY 0xFFF0000000000000ULL   /* dkey(+inf) */
#define POPKEY 0xFFFFFFFFFFFFFFFFULL   /* > INFKEY: excluded from argmin */

// ---------------------------------------------------------------------------
// Kernel 2: Jonker-Volgenant, one CTA per batch. n=128 rows, m=4096 cols.
// Row-min warm start on u (unconstrained dual): v stays <= 0 and nonzero only
// on matched columns -> rectangular dual feasibility + CS preserved -> exact
// optimum (a.s. unique => matches reference). One barrier per Dijkstra step.
// ---------------------------------------------------------------------------
__global__ __launch_bounds__(LSA_T) void lsa_kernel(float* __restrict__ out) {
    const int b   = blockIdx.x;
    const int tid = threadIdx.x;

    __shared__ double             u[M_];
    __shared__ unsigned long long red_key[2][NW_]; // parity double-buffer
    __shared__ int                red_idx[2][NW_];
    __shared__ unsigned long long hist_k[M_ + 1];  // pop-time min key
    __shared__ short              hist_j[M_ + 1];  // popped column
    __shared__ short              col4row[M_];     // row -> col (or -1)
    __shared__ signed char        row4col[N_];     // col -> row (or -1)
    __shared__ unsigned char      path_sm[N_];     // predecessor row per col

    const float* costb = g_cost + (size_t)b * M_ * N_;

    double v_loc[KPT];                             // v[tid + 512k], starts 0
    #pragma unroll
    for (int k = 0; k < KPT; ++k) v_loc[k] = 0.0;

    for (int j = tid; j < N_; j += LSA_T) row4col[j] = -1;
    if (tid < M_) {
        u[tid] = (double)g_umin[b * M_ + tid];     // row-min warm start
        col4row[tid] = -1;
    }
    __syncthreads();

    for (int cur = 0; cur < M_; ++cur) {
        unsigned long long sk[KPT];                // key(shortest[j]), registers
        #pragma unroll
        for (int k = 0; k < KPT; ++k) sk[k] = INFKEY;
        unsigned int popmask = 0;                  // bit k: column tid+512k popped

        int    i    = cur;
        double mv   = 0.0;
        double u_i  = u[cur];
        int    S    = 0;
        int    sink = -1;

        // ---- Dijkstra: ONE barrier per step ----
        while (true) {
            const double muv  = mv - u_i;          // uniform
            const float* crow = costb + (size_t)i * N_;

            float c[KPT];
            #pragma unroll
            for (int k = 0; k < KPT; ++k) c[k] = __ldg(crow + tid + k * LSA_T);

            double t[KPT];                         // off the L2-latency chain
            #pragma unroll
            for (int k = 0; k < KPT; ++k) t[k] = muv - v_loc[k];

            #pragma unroll
            for (int k = 0; k < KPT; ++k) {
                const int j = tid + k * LSA_T;
                double r = t[k] + (double)c[k];    // 1 DADD after load
                unsigned long long rk = dkey(r);
                if (!(popmask & (1u << k)) && rk < sk[k]) {
                    sk[k] = rk;
                    path_sm[j] = (unsigned char)i;
                }
            }

            // per-thread argmin over 8 register keys (ascending k => lowest j)
            unsigned long long bkey = sk[0];
            int                bk   = 0;
            #pragma unroll
            for (int k = 1; k < KPT; ++k)
                if (sk[k] < bkey) { bkey = sk[k]; bk = k; }
            int bidx = tid + bk * LSA_T;

            // warp argmin (tie-break: smaller column index)
            #pragma unroll
            for (int off = 16; off > 0; off >>= 1) {
                unsigned long long ok = __shfl_down_sync(0xffffffffu, bkey, off);
                int                oi = __shfl_down_sync(0xffffffffu, bidx, off);
                if (ok < bkey || (ok == bkey && oi < bidx)) { bkey = ok; bidx = oi; }
            }
            const int p = S & 1;
            if ((tid & 31) == 0) { red_key[p][tid >> 5] = bkey; red_idx[p][tid >> 5] = bidx; }
            __syncthreads();

            // tree-scan the 16 warp minima (lexicographic min is associative)
            unsigned long long kk[NW_];
            int                jj[NW_];
            #pragma unroll
            for (int w = 0; w < NW_; ++w) { kk[w] = red_key[p][w]; jj[w] = red_idx[p][w]; }
            #pragma unroll
            for (int st = NW_ / 2; st > 0; st >>= 1)
                #pragma unroll
                for (int w = 0; w < NW_ / 2; ++w)
                    if (w < st) {
                        if (kk[w + st] < kk[w] ||
                            (kk[w + st] == kk[w] && jj[w + st] < jj[w])) {
                            kk[w] = kk[w + st]; jj[w] = jj[w + st];
                        }
                    }
            const unsigned long long kmin = kk[0];
            const int                jmin = jj[0];

            if (tid == 0) { hist_k[S] = kmin; hist_j[S] = (short)jmin; }
            S++;

            // owner retires the popped column
            if ((jmin & (LSA_T - 1)) == tid) {
                #pragma unroll
                for (int k = 0; k < KPT; ++k)
                    if (jmin == tid + k * LSA_T) {
                        sk[k] = POPKEY;
                        popmask |= (1u << k);
                    }
            }

            mv = dunkey(kmin);
            int rc = row4col[jmin];
            if (rc < 0) { sink = jmin; break; }
            i   = rc;
            u_i = u[i];
        }
        __syncthreads();    // hist + path + relax complete everywhere

        // ---- dual update from pop history ----
        const double mvf = mv;
        if (tid == cur) u[cur] += mvf;
        if (tid < S - 1) {                         // non-sink pops
            int js = hist_j[tid];
            int r  = row4col[js];                  // pre-augment matching
            u[r] += mvf - dunkey(hist_k[tid]);
        }
        for (int s = 0; s < S; ++s) {              // v over popped cols (<= 0)
            int js = hist_j[s];
            if ((js & (LSA_T - 1)) == tid) {
                double d  = mvf - dunkey(hist_k[s]);
                int    kq = js >> 9;
                #pragma unroll
                for (int k = 0; k < KPT; ++k)      // constant-index only
                    if (kq == k) v_loc[k] -= d;
            }
        }
        __syncthreads();    // dual reads of row4col done before augment writes

        // ---- augment along alternating path ----
        if (tid == 0) {
            int j = sink;
            while (true) {
                int i2 = path_sm[j];
                row4col[j] = (signed char)i2;
                int t2 = col4row[i2]; col4row[i2] = (short)j; j = t2;
                if (i2 == cur) break;
            }
        }
        __syncthreads();
    }

    // ---- emit (batch, src, tgt) as FLOAT32, sorted by src ----
    if (tid < M_) {
        int c = col4row[tid];
        int rank = 0;
        #pragma unroll 8
        for (int k = 0; k < M_; ++k) rank += (col4row[k] < c);
        int base = b * M_ + rank;
        out[0 * TOT_ + base] = (float)b;
        out[1 * TOT_ + base] = (float)c;
        out[2 * TOT_ + base] = (float)tid;
    }
}

// ---------------------------------------------------------------------------
extern "C" void kernel_launch(void* const* d_in, const int* in_sizes, int n_in,
                              void* d_out, int out_size) {
    const float* ps = (const float*)d_in[0];
    const float* pp = (const float*)d_in[1];
    const int*   sc = (const int*)  d_in[2];
    const float* pt = (const float*)d_in[3];

    cost_kernel<<<B_ * M_, 256>>>(ps, pp, sc, pt);
    lsa_kernel<<<B_, LSA_T>>>((float*)d_out);
}

// round 11
// speedup vs baseline: 2.0979x; 1.3746x over previous
#include <cuda_runtime.h>
#include <math.h>
#include <stdint.h>

#define B_ 32
#define N_ 4096
#define M_ 128
#define TOT_ (B_ * M_)       // 4096 matched pairs total
#define LSA_T 512
#define KPT (N_ / LSA_T)     // 8 columns per thread (strided: j = tid + 512k)
#define NW_ (LSA_T / 32)     // 16 warps

// Cost matrix scratch, stored TRANSPOSED: cost_t[b][m][n] = cost[b][n][m].
__device__ float g_cost[(size_t)B_ * M_ * N_];
// Row minima / argminima of the transposed matrix.
__device__ float g_umin[B_ * M_];
__device__ int   g_amin[B_ * M_];

// ---------------------------------------------------------------------------
// Kernel 1: cost matrix + row-(arg)min (one CTA per (b, m) row).
// ---------------------------------------------------------------------------
__global__ void cost_kernel(const float* __restrict__ ps,
                            const float* __restrict__ pp,
                            const int*   __restrict__ sc,
                            const float* __restrict__ pt) {
    int bm = blockIdx.x;
    int b  = bm >> 7;
    int m  = bm & (M_ - 1);
    int s  = sc[b * M_ + m];
    float qx = pt[(b * M_ + m) * 2 + 0];
    float qy = pt[(b * M_ + m) * 2 + 1];
    float* out = g_cost + (size_t)bm * N_;
    const float2* psb = ((const float2*)ps) + (size_t)b * N_;
    const float2* ppb = ((const float2*)pp) + (size_t)b * N_;

    float lmin = __int_as_float(0x7f800000);
    int   lidx = N_;
    for (int n = threadIdx.x; n < N_; n += blockDim.x) {
        float2 l = psb[n];
        float mx = fmaxf(l.x, l.y);
        float e0 = expf(l.x - mx);
        float e1 = expf(l.y - mx);
        float p  = ((s == 0) ? e0 : e1) / (e0 + e1);
        float2 q = ppb[n];
        float l1 = fabsf(q.x - qx) + fabsf(q.y - qy);
        float c  = -p + l1;
        out[n] = c;
        if (c < lmin) { lmin = c; lidx = n; }      // ascending n: lowest idx kept
    }
    // warp argmin (tie: lowest index)
    #pragma unroll
    for (int off = 16; off > 0; off >>= 1) {
        float ov = __shfl_down_sync(0xffffffffu, lmin, off);
        int   oi = __shfl_down_sync(0xffffffffu, lidx, off);
        if (ov < lmin || (ov == lmin && oi < lidx)) { lmin = ov; lidx = oi; }
    }
    __shared__ float redv[8];
    __shared__ int   redi[8];
    if ((threadIdx.x & 31) == 0) { redv[threadIdx.x >> 5] = lmin; redi[threadIdx.x >> 5] = lidx; }
    __syncthreads();
    if (threadIdx.x == 0) {
        float rv = redv[0]; int ri = redi[0];
        #pragma unroll
        for (int w = 1; w < 8; ++w) {
            if (redv[w] < rv || (redv[w] == rv && redi[w] < ri)) { rv = redv[w]; ri = redi[w]; }
        }
        g_umin[bm] = rv;
        g_amin[bm] = ri;
    }
}

// Order-preserving bijection double <-> uint64 (total order, exact).
__device__ __forceinline__ unsigned long long dkey(double x) {
    unsigned long long u = (unsigned long long)__double_as_longlong(x);
    unsigned long long m = (unsigned long long)((long long)u >> 63);
    return u ^ (m | 0x8000000000000000ULL);
}
__device__ __forceinline__ double dunkey(unsigned long long k) {
    unsigned long long u = (k & 0x8000000000000000ULL)
                         ? (k ^ 0x8000000000000000ULL) : ~k;
    return __longlong_as_double((long long)u);
}

#define INFKEY 0xFFF0000000000000ULL   /* dkey(+inf) */
#define POPKEY 0xFFFFFFFFFFFFFFFFULL   /* > INFKEY: excluded from argmin */

// ---------------------------------------------------------------------------
// Kernel 2: Jonker-Volgenant, one CTA per batch. n=128 rows, m=4096 cols.
// Row-min warm start on u (dual-feasible for the rectangular LP). Greedy
// pre-match when the row's argmin column is free (exactly equivalent to the
// 1-step Dijkstra it replaces). Full Dijkstra otherwise (exact f64).
// ---------------------------------------------------------------------------
__global__ __launch_bounds__(LSA_T) void lsa_kernel(float* __restrict__ out) {
    const int b   = blockIdx.x;
    const int tid = threadIdx.x;

    __shared__ double             u[M_];
    __shared__ uint4              red[2][NW_];     // {key_lo, key_hi, idx, 0}
    __shared__ unsigned long long hist_k[M_ + 1];  // pop-time min key
    __shared__ short              hist_j[M_ + 1];  // popped column
    __shared__ short              col4row[M_];     // row -> col (or -1)
    __shared__ short              s_amin[M_];      // row argmin column
    __shared__ signed char        row4col[N_];     // col -> row (or -1)
    __shared__ unsigned char      path_sm[N_];     // predecessor row per col

    const float* costb = g_cost + (size_t)b * M_ * N_;

    double v_loc[KPT];                             // v[tid + 512k], starts 0
    #pragma unroll
    for (int k = 0; k < KPT; ++k) v_loc[k] = 0.0;

    for (int j = tid; j < N_; j += LSA_T) row4col[j] = -1;
    if (tid < M_) {
        u[tid]       = (double)g_umin[b * M_ + tid];   // row-min warm start
        s_amin[tid]  = (short)g_amin[b * M_ + tid];
        col4row[tid] = -1;
    }
    __syncthreads();

    for (int cur = 0; cur < M_; ++cur) {
        // ---- greedy pre-match: argmin column free => 1-step Dijkstra ----
        const int jstar   = s_amin[cur];
        const int is_free = (row4col[jstar] < 0);  // uniform (prev barrier)
        __syncthreads();                           // reads sealed before write
        if (is_free) {
            row4col[jstar] = (signed char)cur;     // all threads, same value
            col4row[cur]   = (short)jstar;
            __syncthreads();
            continue;
        }

        unsigned long long sk[KPT];                // key(shortest[j]), registers
        #pragma unroll
        for (int k = 0; k < KPT; ++k) sk[k] = INFKEY;
        unsigned int popmask = 0;                  // bit k: column tid+512k popped

        int    i    = cur;
        double mv   = 0.0;
        double u_i  = u[cur];
        int    S    = 0;
        int    sink = -1;

        // ---- Dijkstra: ONE barrier per step ----
        while (true) {
            const float* crow = costb + (size_t)i * N_;

            float c[KPT];                          // loads first: off the chain head
            #pragma unroll
            for (int k = 0; k < KPT; ++k) c[k] = __ldg(crow + tid + k * LSA_T);

            const double muv = mv - u_i;           // uniform
            double t[KPT];
            #pragma unroll
            for (int k = 0; k < KPT; ++k) t[k] = muv - v_loc[k];

            #pragma unroll
            for (int k = 0; k < KPT; ++k) {
                const int j = tid + k * LSA_T;
                double r = t[k] + (double)c[k];    // 1 DADD after load
                unsigned long long rk = dkey(r);
                if (!(popmask & (1u << k)) && rk < sk[k]) {
                    sk[k] = rk;
                    path_sm[j] = (unsigned char)i;
                }
            }

            // per-thread argmin over 8 register keys (ascending k => lowest j)
            unsigned long long bkey = sk[0];
            int                bk   = 0;
            #pragma unroll
            for (int k = 1; k < KPT; ++k)
                if (sk[k] < bkey) { bkey = sk[k]; bk = k; }
            int bidx = tid + bk * LSA_T;

            // warp argmin (tie-break: smaller column index)
            #pragma unroll
            for (int off = 16; off > 0; off >>= 1) {
                unsigned long long ok = __shfl_down_sync(0xffffffffu, bkey, off);
                int                oi = __shfl_down_sync(0xffffffffu, bidx, off);
                if (ok < bkey || (ok == bkey && oi < bidx)) { bkey = ok; bidx = oi; }
            }
            const int p = S & 1;
            if ((tid & 31) == 0)
                red[p][tid >> 5] = make_uint4((unsigned)(bkey & 0xffffffffu),
                                              (unsigned)(bkey >> 32),
                                              (unsigned)bidx, 0u);
            __syncthreads();

            // all threads: load 16 packed slots (LDS.128), tree-reduce in regs
            unsigned long long kk[NW_];
            int                jj[NW_];
            #pragma unroll
            for (int w = 0; w < NW_; ++w) {
                uint4 rw = red[p][w];
                kk[w] = ((unsigned long long)rw.y << 32) | rw.x;
                jj[w] = (int)rw.z;
            }
            #pragma unroll
            for (int st = NW_ / 2; st > 0; st >>= 1)
                #pragma unroll
                for (int w = 0; w < NW_ / 2; ++w)
                    if (w < st) {
                        if (kk[w + st] < kk[w] ||
                            (kk[w + st] == kk[w] && jj[w + st] < jj[w])) {
                            kk[w] = kk[w + st]; jj[w] = jj[w + st];
                        }
                    }
            const unsigned long long kmin = kk[0];
            const int                jmin = jj[0];

            if (tid == 0) { hist_k[S] = kmin; hist_j[S] = (short)jmin; }
            S++;

            // owner retires the popped column
            if ((jmin & (LSA_T - 1)) == tid) {
                #pragma unroll
                for (int k = 0; k < KPT; ++k)
                    if (jmin == tid + k * LSA_T) {
                        sk[k] = POPKEY;
                        popmask |= (1u << k);
                    }
            }

            mv = dunkey(kmin);
            int rc = row4col[jmin];
            if (rc < 0) { sink = jmin; break; }
            i   = rc;
            u_i = u[i];
        }
        __syncthreads();    // hist + path + relax complete everywhere

        // ---- dual update from pop history ----
        const double mvf = mv;
        if (tid == cur) u[cur] += mvf;
        if (tid < S - 1) {                         // non-sink pops
            int js = hist_j[tid];
            int r  = row4col[js];                  // pre-augment matching
            u[r] += mvf - dunkey(hist_k[tid]);
        }
        for (int s = 0; s < S; ++s) {              // v over popped cols (<= 0)
            int js = hist_j[s];
            if ((js & (LSA_T - 1)) == tid) {
                double d  = mvf - dunkey(hist_k[s]);
                int    kq = js >> 9;
                #pragma unroll
                for (int k = 0; k < KPT; ++k)      // constant-index only
                    if (kq == k) v_loc[k] -= d;
            }
        }
        __syncthreads();    // dual reads of row4col done before augment writes

        // ---- augment along alternating path ----
        if (tid == 0) {
            int j = sink;
            while (true) {
                int i2 = path_sm[j];
                row4col[j] = (signed char)i2;
                int t2 = col4row[i2]; col4row[i2] = (short)j; j = t2;
                if (i2 == cur) break;
            }
        }
        __syncthreads();
    }

    // ---- emit (batch, src, tgt) as FLOAT32, sorted by src ----
    if (tid < M_) {
        int c = col4row[tid];
        int rank = 0;
        #pragma unroll 8
        for (int k = 0; k < M_; ++k) rank += (col4row[k] < c);
        int base = b * M_ + rank;
        out[0 * TOT_ + base] = (float)b;
        out[1 * TOT_ + base] = (float)c;
        out[2 * TOT_ + base] = (float)tid;
    }
}

// ---------------------------------------------------------------------------
extern "C" void kernel_launch(void* const* d_in, const int* in_sizes, int n_in,
                              void* d_out, int out_size) {
    const float* ps = (const float*)d_in[0];
    const float* pp = (const float*)d_in[1];
    const int*   sc = (const int*)  d_in[2];
    const float* pt = (const float*)d_in[3];

    cost_kernel<<<B_ * M_, 256>>>(ps, pp, sc, pt);
    lsa_kernel<<<B_, LSA_T>>>((float*)d_out);
}

// round 14
// speedup vs baseline: 2.1667x; 1.0328x over previous
#include <cuda_runtime.h>
#include <math.h>
#include <stdint.h>

#define B_ 32
#define N_ 4096
#define M_ 128
#define TOT_ (B_ * M_)       // 4096 matched pairs total
#define LSA_T 512
#define KPT (N_ / LSA_T)     // 8 columns per thread (strided: j = tid + 512k)
#define NW_ (LSA_T / 32)     // 16 warps

// Cost matrix scratch, stored TRANSPOSED: cost_t[b][m][n] = cost[b][n][m].
__device__ float g_cost[(size_t)B_ * M_ * N_];
__device__ float g_umin[B_ * M_];
__device__ int   g_amin[B_ * M_];

// ---------------------------------------------------------------------------
// Kernel 1: cost matrix + row-(arg)min (one CTA per (b, m) row).
// ---------------------------------------------------------------------------
__global__ void cost_kernel(const float* __restrict__ ps,
                            const float* __restrict__ pp,
                            const int*   __restrict__ sc,
                            const float* __restrict__ pt) {
    int bm = blockIdx.x;
    int b  = bm >> 7;
    int m  = bm & (M_ - 1);
    int s  = sc[b * M_ + m];
    float qx = pt[(b * M_ + m) * 2 + 0];
    float qy = pt[(b * M_ + m) * 2 + 1];
    float* out = g_cost + (size_t)bm * N_;
    const float2* psb = ((const float2*)ps) + (size_t)b * N_;
    const float2* ppb = ((const float2*)pp) + (size_t)b * N_;

    float lmin = __int_as_float(0x7f800000);
    int   lidx = N_;
    for (int n = threadIdx.x; n < N_; n += blockDim.x) {
        float2 l = psb[n];
        float mx = fmaxf(l.x, l.y);
        float e0 = expf(l.x - mx);
        float e1 = expf(l.y - mx);
        float p  = ((s == 0) ? e0 : e1) / (e0 + e1);
        float2 q = ppb[n];
        float l1 = fabsf(q.x - qx) + fabsf(q.y - qy);
        float c  = -p + l1;
        out[n] = c;
        if (c < lmin) { lmin = c; lidx = n; }
    }
    #pragma unroll
    for (int off = 16; off > 0; off >>= 1) {
        float ov = __shfl_down_sync(0xffffffffu, lmin, off);
        int   oi = __shfl_down_sync(0xffffffffu, lidx, off);
        if (ov < lmin || (ov == lmin && oi < lidx)) { lmin = ov; lidx = oi; }
    }
    __shared__ float redv[8];
    __shared__ int   redi[8];
    if ((threadIdx.x & 31) == 0) { redv[threadIdx.x >> 5] = lmin; redi[threadIdx.x >> 5] = lidx; }
    __syncthreads();
    if (threadIdx.x == 0) {
        float rv = redv[0]; int ri = redi[0];
        #pragma unroll
        for (int w = 1; w < 8; ++w)
            if (redv[w] < rv || (redv[w] == rv && redi[w] < ri)) { rv = redv[w]; ri = redi[w]; }
        g_umin[bm] = rv;
        g_amin[bm] = ri;
    }
}

// Order-preserving bijection double <-> uint64 (total order, exact).
__device__ __forceinline__ unsigned long long dkey(double x) {
    unsigned long long u = (unsigned long long)__double_as_longlong(x);
    unsigned long long m = (unsigned long long)((long long)u >> 63);
    return u ^ (m | 0x8000000000000000ULL);
}
__device__ __forceinline__ double dunkey(unsigned long long k) {
    unsigned long long u = (k & 0x8000000000000000ULL)
                         ? (k ^ 0x8000000000000000ULL) : ~k;
    return __longlong_as_double((long long)u);
}

#define INFKEY 0xFFF0000000000000ULL   /* dkey(+inf) */
#define POPKEY 0xFFFFFFFFFFFFFFFFULL   /* > INFKEY: excluded from argmin */

// ---------------------------------------------------------------------------
// Kernel 2: Jonker-Volgenant, one CTA per batch. n=128 rows, m=4096 cols.
// SAME augmentation order + tie-breaks as scipy (rows 0..127, lowest-index
// argmin): required because the L1 cost has exact pairing degeneracies.
// Row-min warm start on u; inline greedy shortcut (provably = scipy's
// 1-step Dijkstra incl. ties). Warp argmin via 3x REDUX.MIN.U32 (exact).
// ---------------------------------------------------------------------------
__global__ __launch_bounds__(LSA_T) void lsa_kernel(float* __restrict__ out) {
    const int b   = blockIdx.x;
    const int tid = threadIdx.x;

    __shared__ double             u[M_];
    __shared__ uint4              red[2][NW_];     // {key_lo, key_hi, idx, 0}
    __shared__ unsigned long long hist_k[M_ + 1];  // pop-time min key
    __shared__ short              hist_j[M_ + 1];  // popped column
    __shared__ short              col4row[M_];     // row -> col (or -1)
    __shared__ short              s_amin[M_];      // row argmin column
    __shared__ signed char        row4col[N_];     // col -> row (or -1)
    __shared__ unsigned char      path_sm[N_];     // predecessor row per col

    const float* costb = g_cost + (size_t)b * M_ * N_;

    double v_loc[KPT];                             // v[tid + 512k], starts 0
    #pragma unroll
    for (int k = 0; k < KPT; ++k) v_loc[k] = 0.0;

    for (int j = tid; j < N_; j += LSA_T) row4col[j] = -1;
    if (tid < M_) {
        u[tid]       = (double)g_umin[b * M_ + tid];   // row-min warm start
        s_amin[tid]  = (short)g_amin[b * M_ + tid];
        col4row[tid] = -1;
    }
    __syncthreads();

    for (int cur = 0; cur < M_; ++cur) {
        // ---- greedy shortcut: argmin column free => scipy's 1-step Dijkstra ----
        const int jstar   = s_amin[cur];
        const int is_free = (row4col[jstar] < 0);  // uniform (prev barrier)
        __syncthreads();                           // reads sealed before write
        if (is_free) {
            row4col[jstar] = (signed char)cur;     // all threads, same value
            col4row[cur]   = (short)jstar;
            __syncthreads();
            continue;
        }

        unsigned long long sk[KPT];                // key(shortest[j]), registers
        #pragma unroll
        for (int k = 0; k < KPT; ++k) sk[k] = INFKEY;
        unsigned int popmask = 0;                  // bit k: column tid+512k popped

        int    i    = cur;
        double mv   = 0.0;
        double u_i  = u[cur];
        int    S    = 0;
        int    sink = -1;

        // ---- Dijkstra: ONE barrier per step ----
        while (true) {
            const float* crow = costb + (size_t)i * N_;

            float c[KPT];                          // loads first: off the chain head
            #pragma unroll
            for (int k = 0; k < KPT; ++k) c[k] = __ldg(crow + tid + k * LSA_T);

            const double muv = mv - u_i;           // uniform
            double t[KPT];
            #pragma unroll
            for (int k = 0; k < KPT; ++k) t[k] = muv - v_loc[k];

            #pragma unroll
            for (int k = 0; k < KPT; ++k) {
                const int j = tid + k * LSA_T;
                double r = t[k] + (double)c[k];    // 1 DADD after load
                unsigned long long rk = dkey(r);
                if (!(popmask & (1u << k)) && rk < sk[k]) {
                    sk[k] = rk;
                    path_sm[j] = (unsigned char)i;
                }
            }

            // per-thread argmin over 8 register keys (strict <, ascending k
            // => lowest column index kept on ties)
            unsigned long long bkey = sk[0];
            int                bk   = 0;
            #pragma unroll
            for (int k = 1; k < KPT; ++k)
                if (sk[k] < bkey) { bkey = sk[k]; bk = k; }
            int bidx = tid + bk * LSA_T;

            // warp argmin via 3 chained REDUX.MIN.U32 (exact 64-bit lex order,
            // tie-break to the smallest column index)
            unsigned hi   = (unsigned)(bkey >> 32);
            unsigned hmin = __reduce_min_sync(0xffffffffu, hi);
            unsigned loin = (hi == hmin) ? (unsigned)bkey : 0xffffffffu;
            unsigned lmin = __reduce_min_sync(0xffffffffu, loin);
            unsigned idin = (hi == hmin && (unsigned)bkey == lmin)
                          ? (unsigned)bidx : 0xffffffffu;
            unsigned jw   = __reduce_min_sync(0xffffffffu, idin);

            const int p = S & 1;
            if ((tid & 31) == 0)
                red[p][tid >> 5] = make_uint4(lmin, hmin, jw, 0u);
            __syncthreads();

            // all threads: load 16 packed slots (LDS.128), tree-reduce in regs
            unsigned long long kk[NW_];
            int                jj[NW_];
            #pragma unroll
            for (int w = 0; w < NW_; ++w) {
                uint4 rw = red[p][w];
                kk[w] = ((unsigned long long)rw.y << 32) | rw.x;
                jj[w] = (int)rw.z;
            }
            #pragma unroll
            for (int st = NW_ / 2; st > 0; st >>= 1)
                #pragma unroll
                for (int w = 0; w < NW_ / 2; ++w)
                    if (w < st) {
                        if (kk[w + st] < kk[w] ||
                            (kk[w + st] == kk[w] && jj[w + st] < jj[w])) {
                            kk[w] = kk[w + st]; jj[w] = jj[w + st];
                        }
                    }
            const unsigned long long kmin = kk[0];
            const int                jmin = jj[0];

            if (tid == 0) { hist_k[S] = kmin; hist_j[S] = (short)jmin; }
            S++;

            // owner retires the popped column
            if ((jmin & (LSA_T - 1)) == tid) {
                #pragma unroll
                for (int k = 0; k < KPT; ++k)
                    if (jmin == tid + k * LSA_T) {
                        sk[k] = POPKEY;
                        popmask |= (1u << k);
                    }
            }

            mv = dunkey(kmin);
            int rc = row4col[jmin];
            if (rc < 0) { sink = jmin; break; }
            i   = rc;
            u_i = u[i];
        }
        __syncthreads();    // hist + path + relax complete everywhere

        // ---- dual update from pop history ----
        const double mvf = mv;
        if (tid == cur) u[cur] += mvf;
        if (tid < S - 1) {                         // non-sink pops
            int js = hist_j[tid];
            int r  = row4col[js];                  // pre-augment matching
            u[r] += mvf - dunkey(hist_k[tid]);
        }
        for (int s = 0; s < S; ++s) {              // v over popped cols (<= 0)
            int js = hist_j[s];
            if ((js & (LSA_T - 1)) == tid) {
                double d  = mvf - dunkey(hist_k[s]);
                int    kq = js >> 9;
                #pragma unroll
                for (int k = 0; k < KPT; ++k)      // constant-index only
                    if (kq == k) v_loc[k] -= d;
            }
        }
        __syncthreads();    // dual reads of row4col done before augment writes

        // ---- augment along alternating path ----
        if (tid == 0) {
            int j = sink;
            while (true) {
                int i2 = path_sm[j];
                row4col[j] = (signed char)i2;
                int t2 = col4row[i2]; col4row[i2] = (short)j; j = t2;
                if (i2 == cur) break;
            }
        }
        __syncthreads();
    }

    // ---- emit (batch, src, tgt) as FLOAT32, sorted by src ----
    if (tid < M_) {
        int c = col4row[tid];
        int rank = 0;
        #pragma unroll 8
        for (int k = 0; k < M_; ++k) rank += (col4row[k] < c);
        int base = b * M_ + rank;
        out[0 * TOT_ + base] = (float)b;
        out[1 * TOT_ + base] = (float)c;
        out[2 * TOT_ + base] = (float)tid;
    }
}

// ---------------------------------------------------------------------------
extern "C" void kernel_launch(void* const* d_in, const int* in_sizes, int n_in,
                              void* d_out, int out_size) {
    const float* ps = (const float*)d_in[0];
    const float* pp = (const float*)d_in[1];
    const int*   sc = (const int*)  d_in[2];
    const float* pt = (const float*)d_in[3];

    cost_kernel<<<B_ * M_, 256>>>(ps, pp, sc, pt);
    lsa_kernel<<<B_, LSA_T>>>((float*)d_out);
}